// round 9
// baseline (speedup 1.0000x reference)
#include <cuda_runtime.h>
#include <cuda_fp16.h>
#include <math.h>
#include <stdint.h>

// ===========================================================================
// TxtNet, fp16 HMMA.16816 with FP16 accumulation (full-rate tensor pipe on
// sm_103a; fp32-accum mma.sync is half-rate) + per-chunk promotion to fp32.
// cp.async.bulk feeds; producer/consumer full/empty mbarriers (R7 scheme).
// Chunk-major pre-swizzled GMEM layouts. Conv: 4 GEMMs, K=ntap*320.
// SLP: 16384 x 1216 x 512 with the x5==x3 fold.
// ===========================================================================

#define P_TOT 16384

// conv smem: A 16K + B 20K per buffer, 5 buffers
#define CH_A 0
#define CH_B 16384
#define CH_BUF 36864
#define C_NBUF 5
#define CONV_SMEM (C_NBUF * CH_BUF + 128)
// slp smem: A 16K + B 16K per buffer, 6 buffers
#define SL_A 0
#define SL_B 16384
#define SL_BUF 32768
#define S_NBUF 6
#define SLP_SMEM (S_NBUF * SL_BUF + 128)

// ------------------------- device scratch (zero-init) ----------------------
__device__ __half g_xc[32 * 5 * 528 * 64];    // [b][kc][row 528 pad][64] sw(row&7)
__device__ __half g_wcc[65 * 320 * 64];       // [slab][oc][64] sw(oc&7)
__device__ __half g_hc[19 * 16384 * 64];      // [kc][pos][64] sw(pos&7)
__device__ __half g_wec[19 * 512 * 64];       // [kc][oc][64] sw(oc&7)
__device__ float g_bconv[1200];

__constant__ int c_off[13] = {0,  0, 1,  -1, 0, 1,  -3, -2, -1, 0, 1, 2, 3};
__constant__ int c_base[4] = {0, 1, 3, 6};
__constant__ int c_nch[4]  = {5, 10, 15, 35};
__constant__ int c_sb[4]   = {0, 5, 15, 30};

// ------------------------- asm helpers -------------------------------------
__device__ __forceinline__ uint32_t smem_u32(const void* p) {
    uint32_t a;
    asm("{ .reg .u64 t; cvta.to.shared.u64 t, %1; cvt.u32.u64 %0, t; }"
        : "=r"(a) : "l"(p));
    return a;
}
#define BULK_G2S(dst, src, bytes, mbar)                                        \
    asm volatile(                                                              \
        "cp.async.bulk.shared::cluster.global.mbarrier::complete_tx::bytes "   \
        "[%0], [%1], %2, [%3];"                                                \
        :: "r"(dst), "l"(src), "r"(bytes), "r"(mbar) : "memory")
#define MBAR_INIT(a, c) \
    asm volatile("mbarrier.init.shared.b64 [%0], %1;" :: "r"(a), "r"(c) : "memory")
#define MBAR_EXPECT_TX(a, b) \
    asm volatile("mbarrier.arrive.expect_tx.shared.b64 _, [%0], %1;" \
                 :: "r"(a), "r"(b) : "memory")
#define MBAR_ARRIVE(a) \
    asm volatile("mbarrier.arrive.shared.b64 _, [%0];" :: "r"(a) : "memory")
#define FENCE_ASYNC() \
    asm volatile("fence.proxy.async.shared::cta;" ::: "memory")
__device__ __forceinline__ void mbar_wait(uint32_t a, uint32_t ph) {
    asm volatile(
        "{\n .reg .pred P;\nW%=:\n"
        " mbarrier.try_wait.parity.acquire.cta.shared::cta.b64 P, [%0], %1, 0x989680;\n"
        " @!P bra W%=;\n}"
        :: "r"(a), "r"(ph) : "memory");
}
#define LDSM4(R, A) \
    asm volatile("ldmatrix.sync.aligned.m8n8.x4.shared.b16 {%0,%1,%2,%3}, [%4];" \
                 : "=r"((R)[0]), "=r"((R)[1]), "=r"((R)[2]), "=r"((R)[3]) : "r"(A))
#define LDSM2(R, A) \
    asm volatile("ldmatrix.sync.aligned.m8n8.x2.shared.b16 {%0,%1}, [%2];" \
                 : "=r"((R)[0]), "=r"((R)[1]) : "r"(A))

// fp16-accumulate MMA: D(f16x2 x2) = A*B + D. Full-rate on sm_103a.
__device__ __forceinline__ void mma16816h(uint32_t* d, const uint32_t* a,
                                          const uint32_t* b) {
    asm volatile(
        "mma.sync.aligned.m16n8k16.row.col.f16.f16.f16.f16 "
        "{%0,%1}, {%2,%3,%4,%5}, {%6,%7}, {%0,%1};"
        : "+r"(d[0]), "+r"(d[1])
        : "r"(a[0]), "r"(a[1]), "r"(a[2]), "r"(a[3]), "r"(b[0]), "r"(b[1]));
}

// ------------------------- core compute ------------------------------------
// One K=64 chunk: accumulate in fp16 (4 chained MMAs), promote to fp32 accs.
template <int MT, int NT>
__device__ __forceinline__ void compute_buf(uint32_t Ah, uint32_t Bh,
                                            float (&acc)[MT][NT][4],
                                            int wm, int wn, int lane, int rmA) {
    const int hi16 = lane >> 4;
    const int sbB = (lane >> 3) & 1;
    const int rmB = lane & 7;
    const uint32_t aRow  = (uint32_t)(wm * (MT * 16) + (lane & 15)) * 128;
    const uint32_t bRow  = (uint32_t)(wn * (NT * 8) + (lane & 7) +
                                      ((lane >> 4) & 1) * 8) * 128;
    const uint32_t bRow2 = (uint32_t)(wn * (NT * 8) + (NT - 1) * 8 +
                                      (lane & 7)) * 128;
    uint32_t cac[MT][NT][2];
#pragma unroll
    for (int mt = 0; mt < MT; ++mt)
#pragma unroll
        for (int nt = 0; nt < NT; ++nt) { cac[mt][nt][0] = 0; cac[mt][nt][1] = 0; }

#pragma unroll
    for (int kk = 0; kk < 4; ++kk) {
        const uint32_t sA = (uint32_t)(((kk * 2 + hi16) ^ rmA) << 4);
        const uint32_t sB = (uint32_t)(((kk * 2 + sbB) ^ rmB) << 4);
        uint32_t ah[MT][4];
#pragma unroll
        for (int mt = 0; mt < MT; ++mt) {
            LDSM4(ah[mt], Ah + aRow + mt * 2048 + sA);
        }
#pragma unroll
        for (int p = 0; p < NT / 2; ++p) {
            uint32_t bh[4];
            LDSM4(bh, Bh + bRow + p * 2048 + sB);
#pragma unroll
            for (int q = 0; q < 2; ++q)
#pragma unroll
                for (int mt = 0; mt < MT; ++mt)
                    mma16816h(cac[mt][p * 2 + q], ah[mt], bh + q * 2);
        }
        if (NT & 1) {
            uint32_t bh[2];
            LDSM2(bh, Bh + bRow2 + sB);
#pragma unroll
            for (int mt = 0; mt < MT; ++mt)
                mma16816h(cac[mt][NT - 1], ah[mt], bh);
        }
    }
    // promote chunk partials to fp32
#pragma unroll
    for (int mt = 0; mt < MT; ++mt)
#pragma unroll
        for (int nt = 0; nt < NT; ++nt) {
            float2 f0 = __half22float2(*reinterpret_cast<__half2*>(&cac[mt][nt][0]));
            float2 f1 = __half22float2(*reinterpret_cast<__half2*>(&cac[mt][nt][1]));
            acc[mt][nt][0] += f0.x; acc[mt][nt][1] += f0.y;
            acc[mt][nt][2] += f1.x; acc[mt][nt][3] += f1.y;
        }
}

// ------------------------- prep kernels ------------------------------------
__global__ void prep_x(const float* __restrict__ x) {
    int idx = blockIdx.x * 256 + threadIdx.x;
    if (idx >= 32 * 5 * 528 * 64) return;
    int j = idx & 63;
    int rest = idx >> 6;
    int r = rest % 528; rest /= 528;
    int kc = rest % 5;
    int b = rest / 5;
    int rr = r - 8; rr = rr < 0 ? 0 : (rr > 511 ? 511 : rr);
    int c = kc * 64 + j;
    float v = (c < 300) ? x[((size_t)(b * 512 + rr)) * 300 + c] : 0.f;
    int pir = (((j >> 3) ^ (r & 7)) << 3) | (j & 7);
    g_xc[((size_t)((b * 5 + kc) * 528 + r)) * 64 + pir] = __float2half_rn(v);
}

__global__ void prep_wc(const float* __restrict__ w1, const float* __restrict__ w2,
                        const float* __restrict__ w3, const float* __restrict__ w7) {
    int idx = blockIdx.x * 256 + threadIdx.x;
    if (idx >= 65 * 320 * 64) return;
    int j = idx & 63;
    int oc = (idx >> 6) % 320;
    int s = (idx >> 6) / 320;
    int conv = (s < 5) ? 0 : (s < 15) ? 1 : (s < 30) ? 2 : 3;
    int sb = (conv == 0) ? 0 : (conv == 1) ? 5 : (conv == 2) ? 15 : 30;
    int rel = s - sb;
    int tap = rel / 5, kc = rel % 5;
    int ic = kc * 64 + j;
    float v = 0.f;
    if (oc < 300 && ic < 300) {
        if (conv == 0)      v = w1[(oc * 300 + ic)];
        else if (conv == 1) v = w2[(oc * 300 + ic) * 2 + tap];
        else if (conv == 2) v = w3[(oc * 300 + ic) * 3 + tap];
        else                v = w7[(oc * 300 + ic) * 7 + tap];
    }
    int pir = (((j >> 3) ^ (oc & 7)) << 3) | (j & 7);
    g_wcc[((size_t)(s * 320 + oc)) * 64 + pir] = __float2half_rn(v);
}

__global__ void prep_we(const float* __restrict__ slp_w,
                        const float* __restrict__ b1, const float* __restrict__ b2,
                        const float* __restrict__ b3, const float* __restrict__ b7) {
    int idx = blockIdx.x * 256 + threadIdx.x;
    if (idx < 19 * 512 * 64) {
        int j = idx & 63;
        int oc = (idx >> 6) & 511;
        int kc = idx >> 15;
        int ic = kc * 64 + j;
        float v = 0.f;
        if (ic < 600)       v = slp_w[oc * 1500 + ic];
        else if (ic < 900)  v = slp_w[oc * 1500 + ic] + slp_w[oc * 1500 + ic + 300];
        else if (ic < 1200) v = slp_w[oc * 1500 + ic + 300];
        int pir = (((j >> 3) ^ (oc & 7)) << 3) | (j & 7);
        g_wec[((size_t)(kc * 512 + oc)) * 64 + pir] = __float2half_rn(v);
    }
    if (idx < 1200) {
        int conv = idx / 300, oc = idx % 300;
        const float* b = (conv == 0) ? b1 : (conv == 1) ? b2 : (conv == 2) ? b3 : b7;
        g_bconv[idx] = b[oc];
    }
}

// ------------------------- conv GEMM kernel (BM=128, BN=160) ---------------
__global__ __launch_bounds__(512, 1)
void conv_mma_kernel() {
    extern __shared__ char sm[];
    const uint32_t smb = smem_u32(sm);
    const uint32_t mbF = smb + C_NBUF * CH_BUF;          // full barriers
    const uint32_t mbE = mbF + C_NBUF * 8;               // empty barriers
    const int tid = threadIdx.x, lane = tid & 31, wid = tid >> 5;
    const int wm = wid & 3, wn = wid >> 2;               // 4 x 4 warps
    const int quad = lane >> 2, kp2 = (lane & 3) * 2;

    const int conv = 3 - (int)(blockIdx.x >> 1);         // long convs first
    const int oc0  = (blockIdx.x & 1) * 160;
    const int pos0 = blockIdx.y * 128;
    const int bat = pos0 >> 9, l0 = pos0 & 511;
    const int nc = c_nch[conv];
    const int sbase = c_sb[conv];
    const int tb = c_base[conv];

    if (tid == 0) {
#pragma unroll
        for (int i = 0; i < C_NBUF; ++i) {
            MBAR_INIT(mbF + i * 8, 1);
            MBAR_INIT(mbE + i * 8, 16);
        }
        FENCE_ASYNC();
    }
    __syncthreads();

    float acc[2][5][4];
#pragma unroll
    for (int mt = 0; mt < 2; ++mt)
#pragma unroll
        for (int nt = 0; nt < 5; ++nt)
#pragma unroll
            for (int e = 0; e < 4; ++e) acc[mt][nt][e] = 0.f;

    auto issue = [&](int ch, int buf) {  // thread 0 only
        int tap = ch / 5, kc = ch - tap * 5;
        int dlt = c_off[tb + tap];
        const char* a = (const char*)g_xc +
            ((size_t)((bat * 5 + kc) * 528 + 8 + l0 + dlt)) * 128;
        const char* b = (const char*)g_wcc +
            ((size_t)((sbase + ch) * 320 + oc0)) * 128;
        uint32_t d = smb + buf * CH_BUF;
        uint32_t m = mbF + buf * 8;
        MBAR_EXPECT_TX(m, CH_BUF);
        BULK_G2S(d + CH_A, a, 16384, m);
        BULK_G2S(d + CH_B, b, 20480, m);
    };

    if (tid == 0) {
#pragma unroll
        for (int i = 0; i < C_NBUF; ++i)
            if (i < nc) issue(i, i);
    }

    int buf = 0, ph = 0;
    for (int ch = 0; ch < nc; ++ch) {
        mbar_wait(mbF + buf * 8, ph);
        int tap = ch / 5;
        int adj = (8 + c_off[tb + tap]) & 7;             // A swizzle phase
        int rmA = ((lane & 15) + adj) & 7;
        uint32_t d = smb + buf * CH_BUF;
        compute_buf<2, 5>(d + CH_A, d + CH_B, acc, wm, wn, lane, rmA);
        __syncwarp();
        if (lane == 0) MBAR_ARRIVE(mbE + buf * 8);
        if (tid == 0 && ch + C_NBUF < nc) {
            mbar_wait(mbE + buf * 8, ph);                // all 16 warps done
            issue(ch + C_NBUF, buf);
        }
        if (++buf == C_NBUF) { buf = 0; ph ^= 1; }
    }

    // epilogue: tanh(acc + bias) -> chunked+swizzled fp16 h
#pragma unroll
    for (int mt = 0; mt < 2; ++mt) {
        int r0 = pos0 + wm * 32 + mt * 16 + quad;
#pragma unroll
        for (int nt = 0; nt < 5; ++nt) {
            int col = oc0 + wn * 40 + nt * 8 + kp2;
            if (col >= 300) continue;
            int gc = conv * 300 + col;
            int kc = gc >> 6, j = gc & 63;
            float bi0 = g_bconv[gc], bi1 = g_bconv[gc + 1];
#pragma unroll
            for (int half = 0; half < 2; ++half) {
                int r = r0 + half * 8;
                __half2 hv;
                hv.x = __float2half_rn(tanhf(acc[mt][nt][half * 2 + 0] + bi0));
                hv.y = __float2half_rn(tanhf(acc[mt][nt][half * 2 + 1] + bi1));
                int pir = (((j >> 3) ^ (r & 7)) << 3) | (j & 7);
                *(__half2*)(g_hc + ((size_t)kc * 16384 + r) * 64 + pir) = hv;
            }
        }
    }
}

// ------------------------- SLP GEMM kernel (BM=128, BN=128) ----------------
__global__ __launch_bounds__(512, 1)
void slp_mma_kernel(const float* __restrict__ slp_b, float* __restrict__ out) {
    extern __shared__ char sm[];
    const uint32_t smb = smem_u32(sm);
    const uint32_t mbF = smb + S_NBUF * SL_BUF;
    const uint32_t mbE = mbF + S_NBUF * 8;
    const int tid = threadIdx.x, lane = tid & 31, wid = tid >> 5;
    const int wm = wid & 3, wn = wid >> 2;
    const int quad = lane >> 2, kp2 = (lane & 3) * 2;
    const int oc0  = blockIdx.x * 128;
    const int pos0 = blockIdx.y * 128;
    const int nc = 19;
    const int rmA = lane & 7;

    if (tid == 0) {
#pragma unroll
        for (int i = 0; i < S_NBUF; ++i) {
            MBAR_INIT(mbF + i * 8, 1);
            MBAR_INIT(mbE + i * 8, 16);
        }
        FENCE_ASYNC();
    }
    __syncthreads();

    float acc[2][4][4];
#pragma unroll
    for (int mt = 0; mt < 2; ++mt)
#pragma unroll
        for (int nt = 0; nt < 4; ++nt)
#pragma unroll
            for (int e = 0; e < 4; ++e) acc[mt][nt][e] = 0.f;

    auto issue = [&](int ch, int buf) {
        const char* a = (const char*)g_hc + ((size_t)ch * 16384 + pos0) * 128;
        const char* b = (const char*)g_wec + ((size_t)ch * 512 + oc0) * 128;
        uint32_t d = smb + buf * SL_BUF;
        uint32_t m = mbF + buf * 8;
        MBAR_EXPECT_TX(m, SL_BUF);
        BULK_G2S(d + SL_A, a, 16384, m);
        BULK_G2S(d + SL_B, b, 16384, m);
    };

    if (tid == 0) {
#pragma unroll
        for (int i = 0; i < S_NBUF; ++i)
            if (i < nc) issue(i, i);
    }

    int buf = 0, ph = 0;
    for (int ch = 0; ch < nc; ++ch) {
        mbar_wait(mbF + buf * 8, ph);
        uint32_t d = smb + buf * SL_BUF;
        compute_buf<2, 4>(d + SL_A, d + SL_B, acc, wm, wn, lane, rmA);
        __syncwarp();
        if (lane == 0) MBAR_ARRIVE(mbE + buf * 8);
        if (tid == 0 && ch + S_NBUF < nc) {
            mbar_wait(mbE + buf * 8, ph);
            issue(ch + S_NBUF, buf);
        }
        if (++buf == S_NBUF) { buf = 0; ph ^= 1; }
    }

#pragma unroll
    for (int mt = 0; mt < 2; ++mt) {
        int r0 = pos0 + wm * 32 + mt * 16 + quad;
#pragma unroll
        for (int nt = 0; nt < 4; ++nt) {
            int col = oc0 + wn * 32 + nt * 8 + kp2;
            float bi0 = slp_b[col], bi1 = slp_b[col + 1];
#pragma unroll
            for (int half = 0; half < 2; ++half) {
                int r = r0 + half * 8;
                float2 v;
                v.x = tanhf(acc[mt][nt][half * 2 + 0] + bi0);
                v.y = tanhf(acc[mt][nt][half * 2 + 1] + bi1);
                *(float2*)(out + (size_t)r * 512 + col) = v;
            }
        }
    }
}

// ------------------------- launch ------------------------------------------
extern "C" void kernel_launch(void* const* d_in, const int* in_sizes, int n_in,
                              void* d_out, int out_size) {
    const float* x     = (const float*)d_in[0];
    const float* w1    = (const float*)d_in[1];
    const float* b1    = (const float*)d_in[2];
    const float* w2    = (const float*)d_in[3];
    const float* b2    = (const float*)d_in[4];
    const float* w3    = (const float*)d_in[5];
    const float* b3    = (const float*)d_in[6];
    const float* w7    = (const float*)d_in[7];
    const float* b7    = (const float*)d_in[8];
    const float* slp_w = (const float*)d_in[9];
    const float* slp_b = (const float*)d_in[10];
    float* out = (float*)d_out;

    cudaFuncSetAttribute(conv_mma_kernel, cudaFuncAttributeMaxDynamicSharedMemorySize, CONV_SMEM);
    cudaFuncSetAttribute(slp_mma_kernel,  cudaFuncAttributeMaxDynamicSharedMemorySize, SLP_SMEM);

    prep_x<<<(32 * 5 * 528 * 64 + 255) / 256, 256>>>(x);
    prep_wc<<<(65 * 320 * 64 + 255) / 256, 256>>>(w1, w2, w3, w7);
    prep_we<<<(19 * 512 * 64 + 255) / 256, 256>>>(slp_w, b1, b2, b3, b7);

    conv_mma_kernel<<<dim3(8, 128), 512, CONV_SMEM>>>();
    slp_mma_kernel<<<dim3(4, 128), 512, SLP_SMEM>>>(slp_b, out);
}

// round 10
// speedup vs baseline: 1.0968x; 1.0968x over previous
#include <cuda_runtime.h>
#include <cuda_fp16.h>
#include <math.h>
#include <stdint.h>

// ===========================================================================
// TxtNet, single-term fp16 HMMA.16816 (fp32 accum) fed by cp.async.bulk.
// R10 = R7 (best conv config) + register-fragment double buffering:
// prefetch k-step kk+1's LDSM fragments before issuing kk's MMAs, hiding
// LDSM latency inside the warp instead of relying on warp skew.
// Chunk-major pre-swizzled GMEM layouts. Conv: 4 GEMMs, K=ntap*320.
// SLP: 16384 x 1216 x 512 with the x5==x3 fold.
// ===========================================================================

#define P_TOT 16384

// conv smem: A 16K + B 20K per buffer, 5 buffers
#define CH_A 0
#define CH_B 16384
#define CH_BUF 36864
#define C_NBUF 5
#define CONV_SMEM (C_NBUF * CH_BUF + 128)
// slp smem: A 16K + B 16K per buffer, 6 buffers
#define SL_A 0
#define SL_B 16384
#define SL_BUF 32768
#define S_NBUF 6
#define SLP_SMEM (S_NBUF * SL_BUF + 128)

// ------------------------- device scratch (zero-init) ----------------------
__device__ __half g_xc[32 * 5 * 528 * 64];    // [b][kc][row 528 pad][64] sw(row&7)
__device__ __half g_wcc[65 * 320 * 64];       // [slab][oc][64] sw(oc&7)
__device__ __half g_hc[19 * 16384 * 64];      // [kc][pos][64] sw(pos&7)
__device__ __half g_wec[19 * 512 * 64];       // [kc][oc][64] sw(oc&7)
__device__ float g_bconv[1200];

__constant__ int c_off[13] = {0,  0, 1,  -1, 0, 1,  -3, -2, -1, 0, 1, 2, 3};
__constant__ int c_base[4] = {0, 1, 3, 6};
__constant__ int c_nch[4]  = {5, 10, 15, 35};
__constant__ int c_sb[4]   = {0, 5, 15, 30};

// ------------------------- asm helpers -------------------------------------
__device__ __forceinline__ uint32_t smem_u32(const void* p) {
    uint32_t a;
    asm("{ .reg .u64 t; cvta.to.shared.u64 t, %1; cvt.u32.u64 %0, t; }"
        : "=r"(a) : "l"(p));
    return a;
}
#define BULK_G2S(dst, src, bytes, mbar)                                        \
    asm volatile(                                                              \
        "cp.async.bulk.shared::cluster.global.mbarrier::complete_tx::bytes "   \
        "[%0], [%1], %2, [%3];"                                                \
        :: "r"(dst), "l"(src), "r"(bytes), "r"(mbar) : "memory")
#define MBAR_INIT(a, c) \
    asm volatile("mbarrier.init.shared.b64 [%0], %1;" :: "r"(a), "r"(c) : "memory")
#define MBAR_EXPECT_TX(a, b) \
    asm volatile("mbarrier.arrive.expect_tx.shared.b64 _, [%0], %1;" \
                 :: "r"(a), "r"(b) : "memory")
#define MBAR_ARRIVE(a) \
    asm volatile("mbarrier.arrive.shared.b64 _, [%0];" :: "r"(a) : "memory")
#define FENCE_ASYNC() \
    asm volatile("fence.proxy.async.shared::cta;" ::: "memory")
__device__ __forceinline__ void mbar_wait(uint32_t a, uint32_t ph) {
    asm volatile(
        "{\n .reg .pred P;\nW%=:\n"
        " mbarrier.try_wait.parity.acquire.cta.shared::cta.b64 P, [%0], %1, 0x989680;\n"
        " @!P bra W%=;\n}"
        :: "r"(a), "r"(ph) : "memory");
}
#define LDSM4(R, A) \
    asm volatile("ldmatrix.sync.aligned.m8n8.x4.shared.b16 {%0,%1,%2,%3}, [%4];" \
                 : "=r"((R)[0]), "=r"((R)[1]), "=r"((R)[2]), "=r"((R)[3]) : "r"(A))
#define LDSM2(R, A) \
    asm volatile("ldmatrix.sync.aligned.m8n8.x2.shared.b16 {%0,%1}, [%2];" \
                 : "=r"((R)[0]), "=r"((R)[1]) : "r"(A))

__device__ __forceinline__ void mma16816(float* d, const uint32_t* a,
                                         const uint32_t* b) {
    asm volatile(
        "mma.sync.aligned.m16n8k16.row.col.f32.f16.f16.f32 "
        "{%0,%1,%2,%3}, {%4,%5,%6,%7}, {%8,%9}, {%0,%1,%2,%3};"
        : "+f"(d[0]), "+f"(d[1]), "+f"(d[2]), "+f"(d[3])
        : "r"(a[0]), "r"(a[1]), "r"(a[2]), "r"(a[3]), "r"(b[0]), "r"(b[1]));
}

// ------------------------- core compute ------------------------------------
// Register-fragment double buffering across the 4 k16-steps of a chunk.
template <int MT, int NT>
__device__ __forceinline__ void compute_buf(uint32_t Ah, uint32_t Bh,
                                            float (&acc)[MT][NT][4],
                                            int wm, int wn, int lane, int rmA) {
    const int hi16 = lane >> 4;
    const int sbB = (lane >> 3) & 1;
    const int rmB = lane & 7;
    const uint32_t aRow  = (uint32_t)(wm * (MT * 16) + (lane & 15)) * 128;
    const uint32_t bRow  = (uint32_t)(wn * (NT * 8) + (lane & 7) +
                                      ((lane >> 4) & 1) * 8) * 128;
    const uint32_t bRow2 = (uint32_t)(wn * (NT * 8) + (NT - 1) * 8 +
                                      (lane & 7)) * 128;

    uint32_t ah[2][MT][4];
    uint32_t bf[2][NT][2];

    auto load_k = [&](int kk, int s) {
        const uint32_t sA = (uint32_t)(((kk * 2 + hi16) ^ rmA) << 4);
        const uint32_t sB = (uint32_t)(((kk * 2 + sbB) ^ rmB) << 4);
#pragma unroll
        for (int mt = 0; mt < MT; ++mt)
            LDSM4(ah[s][mt], Ah + aRow + mt * 2048 + sA);
#pragma unroll
        for (int p = 0; p < NT / 2; ++p) {
            uint32_t t4[4];
            LDSM4(t4, Bh + bRow + p * 2048 + sB);
            bf[s][p * 2][0] = t4[0]; bf[s][p * 2][1] = t4[1];
            bf[s][p * 2 + 1][0] = t4[2]; bf[s][p * 2 + 1][1] = t4[3];
        }
        if (NT & 1)
            LDSM2(bf[s][NT - 1], Bh + bRow2 + sB);
    };

    load_k(0, 0);
#pragma unroll
    for (int kk = 0; kk < 4; ++kk) {
        const int cur = kk & 1;
        if (kk < 3) load_k(kk + 1, cur ^ 1);
#pragma unroll
        for (int nt = 0; nt < NT; ++nt)
#pragma unroll
            for (int mt = 0; mt < MT; ++mt)
                mma16816(acc[mt][nt], ah[cur][mt], bf[cur][nt]);
    }
}

// ------------------------- prep kernels ------------------------------------
__global__ void prep_x(const float* __restrict__ x) {
    int idx = blockIdx.x * 256 + threadIdx.x;
    if (idx >= 32 * 5 * 528 * 64) return;
    int j = idx & 63;
    int rest = idx >> 6;
    int r = rest % 528; rest /= 528;
    int kc = rest % 5;
    int b = rest / 5;
    int rr = r - 8; rr = rr < 0 ? 0 : (rr > 511 ? 511 : rr);
    int c = kc * 64 + j;
    float v = (c < 300) ? x[((size_t)(b * 512 + rr)) * 300 + c] : 0.f;
    int pir = (((j >> 3) ^ (r & 7)) << 3) | (j & 7);
    g_xc[((size_t)((b * 5 + kc) * 528 + r)) * 64 + pir] = __float2half_rn(v);
}

__global__ void prep_wc(const float* __restrict__ w1, const float* __restrict__ w2,
                        const float* __restrict__ w3, const float* __restrict__ w7) {
    int idx = blockIdx.x * 256 + threadIdx.x;
    if (idx >= 65 * 320 * 64) return;
    int j = idx & 63;
    int oc = (idx >> 6) % 320;
    int s = (idx >> 6) / 320;
    int conv = (s < 5) ? 0 : (s < 15) ? 1 : (s < 30) ? 2 : 3;
    int sb = (conv == 0) ? 0 : (conv == 1) ? 5 : (conv == 2) ? 15 : 30;
    int rel = s - sb;
    int tap = rel / 5, kc = rel % 5;
    int ic = kc * 64 + j;
    float v = 0.f;
    if (oc < 300 && ic < 300) {
        if (conv == 0)      v = w1[(oc * 300 + ic)];
        else if (conv == 1) v = w2[(oc * 300 + ic) * 2 + tap];
        else if (conv == 2) v = w3[(oc * 300 + ic) * 3 + tap];
        else                v = w7[(oc * 300 + ic) * 7 + tap];
    }
    int pir = (((j >> 3) ^ (oc & 7)) << 3) | (j & 7);
    g_wcc[((size_t)(s * 320 + oc)) * 64 + pir] = __float2half_rn(v);
}

__global__ void prep_we(const float* __restrict__ slp_w,
                        const float* __restrict__ b1, const float* __restrict__ b2,
                        const float* __restrict__ b3, const float* __restrict__ b7) {
    int idx = blockIdx.x * 256 + threadIdx.x;
    if (idx < 19 * 512 * 64) {
        int j = idx & 63;
        int oc = (idx >> 6) & 511;
        int kc = idx >> 15;
        int ic = kc * 64 + j;
        float v = 0.f;
        if (ic < 600)       v = slp_w[oc * 1500 + ic];
        else if (ic < 900)  v = slp_w[oc * 1500 + ic] + slp_w[oc * 1500 + ic + 300];
        else if (ic < 1200) v = slp_w[oc * 1500 + ic + 300];
        int pir = (((j >> 3) ^ (oc & 7)) << 3) | (j & 7);
        g_wec[((size_t)(kc * 512 + oc)) * 64 + pir] = __float2half_rn(v);
    }
    if (idx < 1200) {
        int conv = idx / 300, oc = idx % 300;
        const float* b = (conv == 0) ? b1 : (conv == 1) ? b2 : (conv == 2) ? b3 : b7;
        g_bconv[idx] = b[oc];
    }
}

// ------------------------- conv GEMM kernel (BM=128, BN=160) ---------------
__global__ __launch_bounds__(512, 1)
void conv_mma_kernel() {
    extern __shared__ char sm[];
    const uint32_t smb = smem_u32(sm);
    const uint32_t mbF = smb + C_NBUF * CH_BUF;          // full barriers
    const uint32_t mbE = mbF + C_NBUF * 8;               // empty barriers
    const int tid = threadIdx.x, lane = tid & 31, wid = tid >> 5;
    const int wm = wid & 3, wn = wid >> 2;               // 4 x 4 warps
    const int quad = lane >> 2, kp2 = (lane & 3) * 2;

    const int conv = 3 - (int)(blockIdx.x >> 1);         // long convs first
    const int oc0  = (blockIdx.x & 1) * 160;
    const int pos0 = blockIdx.y * 128;
    const int bat = pos0 >> 9, l0 = pos0 & 511;
    const int nc = c_nch[conv];
    const int sbase = c_sb[conv];
    const int tb = c_base[conv];

    if (tid == 0) {
#pragma unroll
        for (int i = 0; i < C_NBUF; ++i) {
            MBAR_INIT(mbF + i * 8, 1);
            MBAR_INIT(mbE + i * 8, 16);
        }
        FENCE_ASYNC();
    }
    __syncthreads();

    float acc[2][5][4];
#pragma unroll
    for (int mt = 0; mt < 2; ++mt)
#pragma unroll
        for (int nt = 0; nt < 5; ++nt)
#pragma unroll
            for (int e = 0; e < 4; ++e) acc[mt][nt][e] = 0.f;

    auto issue = [&](int ch, int buf) {  // thread 0 only
        int tap = ch / 5, kc = ch - tap * 5;
        int dlt = c_off[tb + tap];
        const char* a = (const char*)g_xc +
            ((size_t)((bat * 5 + kc) * 528 + 8 + l0 + dlt)) * 128;
        const char* b = (const char*)g_wcc +
            ((size_t)((sbase + ch) * 320 + oc0)) * 128;
        uint32_t d = smb + buf * CH_BUF;
        uint32_t m = mbF + buf * 8;
        MBAR_EXPECT_TX(m, CH_BUF);
        BULK_G2S(d + CH_A, a, 16384, m);
        BULK_G2S(d + CH_B, b, 20480, m);
    };

    if (tid == 0) {
#pragma unroll
        for (int i = 0; i < C_NBUF; ++i)
            if (i < nc) issue(i, i);
    }

    int buf = 0, ph = 0;
    for (int ch = 0; ch < nc; ++ch) {
        mbar_wait(mbF + buf * 8, ph);
        int tap = ch / 5;
        int adj = (8 + c_off[tb + tap]) & 7;             // A swizzle phase
        int rmA = ((lane & 15) + adj) & 7;
        uint32_t d = smb + buf * CH_BUF;
        compute_buf<2, 5>(d + CH_A, d + CH_B, acc, wm, wn, lane, rmA);
        __syncwarp();
        if (lane == 0) MBAR_ARRIVE(mbE + buf * 8);
        if (tid == 0 && ch + C_NBUF < nc) {
            mbar_wait(mbE + buf * 8, ph);                // all 16 warps done
            issue(ch + C_NBUF, buf);
        }
        if (++buf == C_NBUF) { buf = 0; ph ^= 1; }
    }

    // epilogue: tanh(acc + bias) -> chunked+swizzled fp16 h
#pragma unroll
    for (int mt = 0; mt < 2; ++mt) {
        int r0 = pos0 + wm * 32 + mt * 16 + quad;
#pragma unroll
        for (int nt = 0; nt < 5; ++nt) {
            int col = oc0 + wn * 40 + nt * 8 + kp2;
            if (col >= 300) continue;
            int gc = conv * 300 + col;
            int kc = gc >> 6, j = gc & 63;
            float bi0 = g_bconv[gc], bi1 = g_bconv[gc + 1];
#pragma unroll
            for (int half = 0; half < 2; ++half) {
                int r = r0 + half * 8;
                __half2 hv;
                hv.x = __float2half_rn(tanhf(acc[mt][nt][half * 2 + 0] + bi0));
                hv.y = __float2half_rn(tanhf(acc[mt][nt][half * 2 + 1] + bi1));
                int pir = (((j >> 3) ^ (r & 7)) << 3) | (j & 7);
                *(__half2*)(g_hc + ((size_t)kc * 16384 + r) * 64 + pir) = hv;
            }
        }
    }
}

// ------------------------- SLP GEMM kernel (BM=128, BN=128) ----------------
__global__ __launch_bounds__(512, 1)
void slp_mma_kernel(const float* __restrict__ slp_b, float* __restrict__ out) {
    extern __shared__ char sm[];
    const uint32_t smb = smem_u32(sm);
    const uint32_t mbF = smb + S_NBUF * SL_BUF;
    const uint32_t mbE = mbF + S_NBUF * 8;
    const int tid = threadIdx.x, lane = tid & 31, wid = tid >> 5;
    const int wm = wid & 3, wn = wid >> 2;
    const int quad = lane >> 2, kp2 = (lane & 3) * 2;
    const int oc0  = blockIdx.x * 128;
    const int pos0 = blockIdx.y * 128;
    const int nc = 19;
    const int rmA = lane & 7;

    if (tid == 0) {
#pragma unroll
        for (int i = 0; i < S_NBUF; ++i) {
            MBAR_INIT(mbF + i * 8, 1);
            MBAR_INIT(mbE + i * 8, 16);
        }
        FENCE_ASYNC();
    }
    __syncthreads();

    float acc[2][4][4];
#pragma unroll
    for (int mt = 0; mt < 2; ++mt)
#pragma unroll
        for (int nt = 0; nt < 4; ++nt)
#pragma unroll
            for (int e = 0; e < 4; ++e) acc[mt][nt][e] = 0.f;

    auto issue = [&](int ch, int buf) {
        const char* a = (const char*)g_hc + ((size_t)ch * 16384 + pos0) * 128;
        const char* b = (const char*)g_wec + ((size_t)ch * 512 + oc0) * 128;
        uint32_t d = smb + buf * SL_BUF;
        uint32_t m = mbF + buf * 8;
        MBAR_EXPECT_TX(m, SL_BUF);
        BULK_G2S(d + SL_A, a, 16384, m);
        BULK_G2S(d + SL_B, b, 16384, m);
    };

    if (tid == 0) {
#pragma unroll
        for (int i = 0; i < S_NBUF; ++i)
            if (i < nc) issue(i, i);
    }

    int buf = 0, ph = 0;
    for (int ch = 0; ch < nc; ++ch) {
        mbar_wait(mbF + buf * 8, ph);
        uint32_t d = smb + buf * SL_BUF;
        compute_buf<2, 4>(d + SL_A, d + SL_B, acc, wm, wn, lane, rmA);
        __syncwarp();
        if (lane == 0) MBAR_ARRIVE(mbE + buf * 8);
        if (tid == 0 && ch + S_NBUF < nc) {
            mbar_wait(mbE + buf * 8, ph);
            issue(ch + S_NBUF, buf);
        }
        if (++buf == S_NBUF) { buf = 0; ph ^= 1; }
    }

#pragma unroll
    for (int mt = 0; mt < 2; ++mt) {
        int r0 = pos0 + wm * 32 + mt * 16 + quad;
#pragma unroll
        for (int nt = 0; nt < 4; ++nt) {
            int col = oc0 + wn * 32 + nt * 8 + kp2;
            float bi0 = slp_b[col], bi1 = slp_b[col + 1];
#pragma unroll
            for (int half = 0; half < 2; ++half) {
                int r = r0 + half * 8;
                float2 v;
                v.x = tanhf(acc[mt][nt][half * 2 + 0] + bi0);
                v.y = tanhf(acc[mt][nt][half * 2 + 1] + bi1);
                *(float2*)(out + (size_t)r * 512 + col) = v;
            }
        }
    }
}

// ------------------------- launch ------------------------------------------
extern "C" void kernel_launch(void* const* d_in, const int* in_sizes, int n_in,
                              void* d_out, int out_size) {
    const float* x     = (const float*)d_in[0];
    const float* w1    = (const float*)d_in[1];
    const float* b1    = (const float*)d_in[2];
    const float* w2    = (const float*)d_in[3];
    const float* b2    = (const float*)d_in[4];
    const float* w3    = (const float*)d_in[5];
    const float* b3    = (const float*)d_in[6];
    const float* w7    = (const float*)d_in[7];
    const float* b7    = (const float*)d_in[8];
    const float* slp_w = (const float*)d_in[9];
    const float* slp_b = (const float*)d_in[10];
    float* out = (float*)d_out;

    cudaFuncSetAttribute(conv_mma_kernel, cudaFuncAttributeMaxDynamicSharedMemorySize, CONV_SMEM);
    cudaFuncSetAttribute(slp_mma_kernel,  cudaFuncAttributeMaxDynamicSharedMemorySize, SLP_SMEM);

    prep_x<<<(32 * 5 * 528 * 64 + 255) / 256, 256>>>(x);
    prep_wc<<<(65 * 320 * 64 + 255) / 256, 256>>>(w1, w2, w3, w7);
    prep_we<<<(19 * 512 * 64 + 255) / 256, 256>>>(slp_w, b1, b2, b3, b7);

    conv_mma_kernel<<<dim3(8, 128), 512, CONV_SMEM>>>();
    slp_mma_kernel<<<dim3(4, 128), 512, SLP_SMEM>>>(slp_b, out);
}